// round 2
// baseline (speedup 1.0000x reference)
#include <cuda_runtime.h>
#include <math.h>

#define BB 32
#define NN 3136
#define CC 384
#define HH 8
#define HD 48
#define NT 196
#define C2 768
#define ROWW 56
#define EPSL 1e-6f
#define NOFF 169

// ---------------- scratch (static device globals; no allocation allowed) ----
__device__ float g_mu[BB * NN];
__device__ float g_rs[BB * NN];
__device__ float g_k[(size_t)BB * NN * CC];     // [b][n][h*HD+d]
__device__ float g_v[(size_t)BB * NN * CC];
__device__ float g_qc1[BB * NT * CC];           // attn1 output
__device__ float g_hm[BB * NT * C2];            // MLP hidden
__device__ float g_qc2[BB * NT * CC];           // MLP output (q_cond2)
__device__ float g_att[BB * NT * CC];           // attn3 output (pre-proj)
__device__ int   g_cent[BB * NT];               // centroid_idx

// ---------------- kernel 1: layernorm row stats --------------------------
__global__ void ln_stats_kernel(const float* __restrict__ x) {
    int row  = blockIdx.x * 8 + (threadIdx.x >> 5);
    int lane = threadIdx.x & 31;
    if (row >= BB * NN) return;
    const float* xr = x + (size_t)row * CC;
    float s = 0.f, sq = 0.f;
    #pragma unroll
    for (int j = 0; j < 3; j++) {               // 384 = 32 lanes * 3 * float4
        float4 v = *(const float4*)(xr + (j * 32 + lane) * 4);
        s  += v.x + v.y + v.z + v.w;
        sq += v.x * v.x + v.y * v.y + v.z * v.z + v.w * v.w;
    }
    #pragma unroll
    for (int o = 16; o > 0; o >>= 1) {
        s  += __shfl_xor_sync(0xffffffffu, s,  o);
        sq += __shfl_xor_sync(0xffffffffu, sq, o);
    }
    if (lane == 0) {
        float mu  = s / (float)CC;
        float var = sq / (float)CC - mu * mu;
        g_mu[row] = mu;
        g_rs[row] = rsqrtf(var + EPSL);
    }
}

// ---------------- double-buffered SGEMM: C[r,c] = sum_k A[r,k]*W[c,k] ------
// BM=BN=128, BK=16, 256 threads, 8x8 per-thread tile, smem double-buffered.
// MODE 0: LN applied on A-load; epilogue splits cols -> g_k / g_v.
// MODE 1: +bias, exact gelu. MODE 2: +bias.
template <int MODE>
__global__ void __launch_bounds__(256, 2) gemm_db(
    const float* __restrict__ A, const float* __restrict__ W,
    float* __restrict__ O1, float* __restrict__ O2,
    const float* __restrict__ bias,
    const float* __restrict__ lnw, const float* __restrict__ lnb,
    int M, int Ncol, int K)
{
    __shared__ __align__(16) float As[2][16][128];
    __shared__ __align__(16) float Bs[2][16][128];

    const int tid     = threadIdx.x;
    const int rowBase = blockIdx.y * 128;
    const int colBase = blockIdx.x * 128;

    const int ldRow = tid & 127;          // A row / W col within tile
    const int ldK   = (tid >> 7) * 8;     // 0 or 8

    float lm = 0.f, lr = 0.f;
    if (MODE == 0) {
        lm = g_mu[rowBase + ldRow];
        lr = g_rs[rowBase + ldRow];
    }
    const float* Ap = A + (size_t)(rowBase + ldRow) * K + ldK;
    const float* Wp = W + (size_t)(colBase + ldRow) * K + ldK;

    float acc[8][8];
    #pragma unroll
    for (int i = 0; i < 8; i++)
        #pragma unroll
        for (int j = 0; j < 8; j++) acc[i][j] = 0.f;

    const int ty = tid >> 4, tx = tid & 15;
    const int ntiles = K >> 4;

    // ---- prologue: tile 0 straight to smem buf 0
    {
        float4 a0 = *(const float4*)(Ap);
        float4 a1 = *(const float4*)(Ap + 4);
        if (MODE == 0) {
            float4 w0 = *(const float4*)(lnw + ldK);
            float4 w1 = *(const float4*)(lnw + ldK + 4);
            float4 b0 = *(const float4*)(lnb + ldK);
            float4 b1 = *(const float4*)(lnb + ldK + 4);
            a0.x = (a0.x - lm) * lr * w0.x + b0.x;
            a0.y = (a0.y - lm) * lr * w0.y + b0.y;
            a0.z = (a0.z - lm) * lr * w0.z + b0.z;
            a0.w = (a0.w - lm) * lr * w0.w + b0.w;
            a1.x = (a1.x - lm) * lr * w1.x + b1.x;
            a1.y = (a1.y - lm) * lr * w1.y + b1.y;
            a1.z = (a1.z - lm) * lr * w1.z + b1.z;
            a1.w = (a1.w - lm) * lr * w1.w + b1.w;
        }
        float4 b0 = *(const float4*)(Wp);
        float4 b1 = *(const float4*)(Wp + 4);
        As[0][ldK + 0][ldRow] = a0.x; As[0][ldK + 1][ldRow] = a0.y;
        As[0][ldK + 2][ldRow] = a0.z; As[0][ldK + 3][ldRow] = a0.w;
        As[0][ldK + 4][ldRow] = a1.x; As[0][ldK + 5][ldRow] = a1.y;
        As[0][ldK + 6][ldRow] = a1.z; As[0][ldK + 7][ldRow] = a1.w;
        Bs[0][ldK + 0][ldRow] = b0.x; Bs[0][ldK + 1][ldRow] = b0.y;
        Bs[0][ldK + 2][ldRow] = b0.z; Bs[0][ldK + 3][ldRow] = b0.w;
        Bs[0][ldK + 4][ldRow] = b1.x; Bs[0][ldK + 5][ldRow] = b1.y;
        Bs[0][ldK + 6][ldRow] = b1.z; Bs[0][ldK + 7][ldRow] = b1.w;
    }
    __syncthreads();

    int buf = 0;
    for (int t = 0; t < ntiles; t++) {
        float4 pa0, pa1, pb0, pb1;
        const bool havenext = (t + 1 < ntiles);
        if (havenext) {
            const int kof = (t + 1) << 4;
            pa0 = *(const float4*)(Ap + kof);
            pa1 = *(const float4*)(Ap + kof + 4);
            pb0 = *(const float4*)(Wp + kof);
            pb1 = *(const float4*)(Wp + kof + 4);
        }

        #pragma unroll
        for (int k = 0; k < 16; k++) {
            float4 a0 = *(const float4*)&As[buf][k][ty * 8];
            float4 a1 = *(const float4*)&As[buf][k][ty * 8 + 4];
            float4 b0 = *(const float4*)&Bs[buf][k][tx * 8];
            float4 b1 = *(const float4*)&Bs[buf][k][tx * 8 + 4];
            float ra[8] = {a0.x, a0.y, a0.z, a0.w, a1.x, a1.y, a1.z, a1.w};
            float rb[8] = {b0.x, b0.y, b0.z, b0.w, b1.x, b1.y, b1.z, b1.w};
            #pragma unroll
            for (int i = 0; i < 8; i++)
                #pragma unroll
                for (int j = 0; j < 8; j++)
                    acc[i][j] += ra[i] * rb[j];
        }

        if (havenext) {
            const int nb  = buf ^ 1;
            const int kof = (t + 1) << 4;
            if (MODE == 0) {
                float4 w0 = *(const float4*)(lnw + kof + ldK);
                float4 w1 = *(const float4*)(lnw + kof + ldK + 4);
                float4 lb0 = *(const float4*)(lnb + kof + ldK);
                float4 lb1 = *(const float4*)(lnb + kof + ldK + 4);
                pa0.x = (pa0.x - lm) * lr * w0.x + lb0.x;
                pa0.y = (pa0.y - lm) * lr * w0.y + lb0.y;
                pa0.z = (pa0.z - lm) * lr * w0.z + lb0.z;
                pa0.w = (pa0.w - lm) * lr * w0.w + lb0.w;
                pa1.x = (pa1.x - lm) * lr * w1.x + lb1.x;
                pa1.y = (pa1.y - lm) * lr * w1.y + lb1.y;
                pa1.z = (pa1.z - lm) * lr * w1.z + lb1.z;
                pa1.w = (pa1.w - lm) * lr * w1.w + lb1.w;
            }
            As[nb][ldK + 0][ldRow] = pa0.x; As[nb][ldK + 1][ldRow] = pa0.y;
            As[nb][ldK + 2][ldRow] = pa0.z; As[nb][ldK + 3][ldRow] = pa0.w;
            As[nb][ldK + 4][ldRow] = pa1.x; As[nb][ldK + 5][ldRow] = pa1.y;
            As[nb][ldK + 6][ldRow] = pa1.z; As[nb][ldK + 7][ldRow] = pa1.w;
            Bs[nb][ldK + 0][ldRow] = pb0.x; Bs[nb][ldK + 1][ldRow] = pb0.y;
            Bs[nb][ldK + 2][ldRow] = pb0.z; Bs[nb][ldK + 3][ldRow] = pb0.w;
            Bs[nb][ldK + 4][ldRow] = pb1.x; Bs[nb][ldK + 5][ldRow] = pb1.y;
            Bs[nb][ldK + 6][ldRow] = pb1.z; Bs[nb][ldK + 7][ldRow] = pb1.w;
            __syncthreads();
        }
        buf ^= 1;
    }

    #pragma unroll
    for (int i = 0; i < 8; i++) {
        const int row = rowBase + ty * 8 + i;
        #pragma unroll
        for (int j = 0; j < 8; j++) {
            const int col = colBase + tx * 8 + j;
            float v = acc[i][j];
            if (MODE == 0) {
                if (col < CC) O1[(size_t)row * CC + col]        = v;
                else          O2[(size_t)row * CC + (col - CC)] = v;
            } else if (MODE == 1) {
                v += bias[col];
                v = v * normcdff(v);           // exact gelu: x * Phi(x)
                O1[(size_t)row * Ncol + col] = v;
            } else {
                v += bias[col];
                O1[(size_t)row * Ncol + col] = v;
            }
        }
    }
}

// ---------------- kernel 3: attn1 + q_cond1 --------------------------------
__global__ void attn1_kernel(const float* __restrict__ q,
                             const int* __restrict__ idx_sub) {
    extern __shared__ float sm[];
    float* ks = sm;               // [NT*HD]
    float* vs = sm + NT * HD;     // [NT*HD]
    const int b = blockIdx.x / HH;
    const int h = blockIdx.x % HH;
    const int tid = threadIdx.x;

    for (int i = tid; i < NT * HD; i += blockDim.x) {
        const int n = i / HD, d = i % HD;
        const size_t src = (size_t)(b * NN + idx_sub[n]) * CC + h * HD + d;
        ks[i] = g_k[src];
        vs[i] = g_v[src];
    }
    __syncthreads();

    const int m = tid;
    if (m < NT) {
        const float scale = rsqrtf((float)HD);
        float qr[HD];
        const float* qp = q + (m * HH + h) * HD;
        #pragma unroll
        for (int d = 0; d < HD; d++) qr[d] = qp[d] * scale;

        float sbuf[NT];
        float mx = -1e30f;
        for (int n = 0; n < NT; n++) {
            const float* kp = ks + n * HD;
            float s = 0.f;
            #pragma unroll
            for (int d = 0; d < HD; d++) s += qr[d] * kp[d];
            sbuf[n] = s;
            mx = fmaxf(mx, s);
        }
        float accd[HD];
        #pragma unroll
        for (int d = 0; d < HD; d++) accd[d] = 0.f;
        float ssum = 0.f;
        for (int n = 0; n < NT; n++) {
            const float w = expf(sbuf[n] - mx);
            ssum += w;
            const float* vp = vs + n * HD;
            #pragma unroll
            for (int d = 0; d < HD; d++) accd[d] += w * vp[d];
        }
        const float inv = 1.f / ssum;
        float* op = g_qc1 + (size_t)(b * NT + m) * CC + h * HD;
        #pragma unroll
        for (int d = 0; d < HD; d++) op[d] = accd[d] * inv;
    }
}

// ---------------- kernel 6: centroid (attn2 argmax) ------------------------
// mean over h of per-head dots == (1/H) * full-C dot -> argmax ignores 1/H.
__global__ void centroid_kernel(const int* __restrict__ idxs) {
    __shared__ float sq[CC];
    __shared__ float sval[256];
    __shared__ int   sidx[256];
    const int bm = blockIdx.x;       // b*NT + m
    const int b  = bm / NT;
    const int tid = threadIdx.x;

    const float* qp = g_qc2 + (size_t)bm * CC;
    for (int i = tid; i < CC; i += blockDim.x) sq[i] = qp[i];
    __syncthreads();

    float best = -1e30f;
    int   bi   = 0x7fffffff;
    for (int n = tid; n < NT; n += blockDim.x) {
        const float* kp = g_k + (size_t)(b * NN + idxs[n]) * CC;
        float s = 0.f;
        for (int c = 0; c < CC; c += 4) {
            float4 k4 = *(const float4*)(kp + c);
            s += sq[c] * k4.x + sq[c + 1] * k4.y + sq[c + 2] * k4.z + sq[c + 3] * k4.w;
        }
        if (s > best || (s == best && n < bi)) { best = s; bi = n; }
    }
    sval[tid] = best; sidx[tid] = bi;
    __syncthreads();
    for (int o = 128; o > 0; o >>= 1) {
        if (tid < o) {
            const float v2 = sval[tid + o];
            const int   i2 = sidx[tid + o];
            if (v2 > sval[tid] || (v2 == sval[tid] && i2 < sidx[tid])) {
                sval[tid] = v2; sidx[tid] = i2;
            }
        }
        __syncthreads();
    }
    if (tid == 0) g_cent[bm] = idxs[sidx[0]];
}

// ---------------- kernel 7: sparse attn3 + AV ------------------------------
// exp(NEG + s - max) underflows to exactly 0.0f, so restricting softmax/AV to
// the <=169 allowed positions is bit-equivalent to the dense reference.
__global__ void __launch_bounds__(192) attn3_kernel() {
    __shared__ float sq[CC];
    __shared__ int   s_adj[NOFF];
    __shared__ unsigned char s_uniq[NOFF];
    __shared__ float s_w[NOFF];
    __shared__ float s_part[4][HD];
    __shared__ float s_sum;

    const int bm = blockIdx.x;
    const int b  = bm / NT;
    const int tid = threadIdx.x;
    const float scale = rsqrtf((float)HD);

    const float* qp = g_qc2 + (size_t)bm * CC;
    for (int i = tid; i < CC; i += blockDim.x) sq[i] = qp[i];
    const int cent = g_cent[bm];
    if (tid < NOFF) {
        const int r = tid / 13 - 6, c = tid % 13 - 6;
        int a = cent + (c - ROWW * r);
        a = max(0, min(NN - 1, a));
        s_adj[tid] = a;
    }
    __syncthreads();
    if (tid < NOFF) {
        const int a = s_adj[tid];
        unsigned char u = 1;
        for (int j = 0; j < tid; j++) if (s_adj[j] == a) { u = 0; break; }
        s_uniq[tid] = u;
    }
    __syncthreads();

    for (int h = 0; h < HH; h++) {
        const float* qh = sq + h * HD;
        for (int n = tid; n < NOFF; n += blockDim.x) {
            float s = -1e30f;
            if (s_uniq[n]) {
                const float* kp = g_k + (size_t)(b * NN + s_adj[n]) * CC + h * HD;
                float acc = 0.f;
                #pragma unroll
                for (int c = 0; c < HD; c += 4) {
                    float4 k4 = *(const float4*)(kp + c);
                    acc += qh[c] * k4.x + qh[c + 1] * k4.y + qh[c + 2] * k4.z + qh[c + 3] * k4.w;
                }
                s = acc * scale;
            }
            s_w[n] = s;
        }
        __syncthreads();
        if (tid < 32) {
            float mx = -1e30f;
            for (int n = tid; n < NOFF; n += 32) mx = fmaxf(mx, s_w[n]);
            #pragma unroll
            for (int o = 16; o > 0; o >>= 1) mx = fmaxf(mx, __shfl_xor_sync(0xffffffffu, mx, o));
            float sum = 0.f;
            for (int n = tid; n < NOFF; n += 32) {
                const float w = expf(s_w[n] - mx);   // dup: exp(-1e30-mx) == 0
                s_w[n] = w;
                sum += w;
            }
            #pragma unroll
            for (int o = 16; o > 0; o >>= 1) sum += __shfl_xor_sync(0xffffffffu, sum, o);
            if (tid == 0) s_sum = sum;
        }
        __syncthreads();
        const float inv = 1.f / s_sum;
        const int g = tid / HD;          // 0..3
        const int d = tid % HD;
        float acc = 0.f;
        for (int n = g; n < NOFF; n += 4)
            acc += s_w[n] * g_v[(size_t)(b * NN + s_adj[n]) * CC + h * HD + d];
        s_part[g][d] = acc;
        __syncthreads();
        if (tid < HD) {
            const float o = (s_part[0][tid] + s_part[1][tid] +
                             s_part[2][tid] + s_part[3][tid]) * inv;
            g_att[(size_t)bm * CC + h * HD + tid] = o;
        }
        __syncthreads();
    }
}

// ---------------- launch ---------------------------------------------------
extern "C" void kernel_launch(void* const* d_in, const int* in_sizes, int n_in,
                              void* d_out, int out_size) {
    const float* x      = (const float*)d_in[0];
    const float* q      = (const float*)d_in[1];
    const float* kv_w   = (const float*)d_in[2];
    const float* proj_w = (const float*)d_in[3];
    const float* proj_b = (const float*)d_in[4];
    const float* ln_w   = (const float*)d_in[5];
    const float* ln_b   = (const float*)d_in[6];
    const float* fc1_w  = (const float*)d_in[7];
    const float* fc1_b  = (const float*)d_in[8];
    const float* fc2_w  = (const float*)d_in[9];
    const float* fc2_b  = (const float*)d_in[10];
    const int* idx_sub  = (const int*)d_in[11];
    const int* idxs     = (const int*)d_in[12];
    float* out = (float*)d_out;

    float *pk, *pv, *pqc1, *phm, *pqc2, *patt;
    cudaGetSymbolAddress((void**)&pk,   g_k);
    cudaGetSymbolAddress((void**)&pv,   g_v);
    cudaGetSymbolAddress((void**)&pqc1, g_qc1);
    cudaGetSymbolAddress((void**)&phm,  g_hm);
    cudaGetSymbolAddress((void**)&pqc2, g_qc2);
    cudaGetSymbolAddress((void**)&patt, g_att);

    // 1. LN row stats
    ln_stats_kernel<<<(BB * NN) / 8, 256>>>(x);

    // 2. fused LN + KV projection (the 59-GFLOP GEMM)
    gemm_db<0><<<dim3(C2 / 128, (BB * NN) / 128), 256>>>(
        x, kv_w, pk, pv, nullptr, ln_w, ln_b, BB * NN, C2, CC);

    // 3. attn1 + q_cond1
    cudaFuncSetAttribute(attn1_kernel,
                         cudaFuncAttributeMaxDynamicSharedMemorySize,
                         2 * NT * HD * (int)sizeof(float));
    attn1_kernel<<<BB * HH, 256, 2 * NT * HD * sizeof(float)>>>(q, idx_sub);

    // 4. MLP
    gemm_db<1><<<dim3(C2 / 128, (BB * NT) / 128), 256>>>(
        pqc1, fc1_w, phm, nullptr, fc1_b, nullptr, nullptr, BB * NT, C2, CC);
    gemm_db<2><<<dim3(CC / 128, (BB * NT) / 128), 256>>>(
        phm, fc2_w, pqc2, nullptr, fc2_b, nullptr, nullptr, BB * NT, CC, C2);

    // 5. centroid argmax (attn2 collapsed to full-C dot)
    centroid_kernel<<<BB * NT, 256>>>(idxs);

    // 6. sparse attn3 + AV
    attn3_kernel<<<BB * NT, 192>>>();

    // 7. output projection
    gemm_db<2><<<dim3(CC / 128, (BB * NT) / 128), 256>>>(
        patt, proj_w, out, nullptr, proj_b, nullptr, nullptr, BB * NT, CC, CC);
}

// round 3
// speedup vs baseline: 1.0424x; 1.0424x over previous
#include <cuda_runtime.h>
#include <math.h>

#define BB 32
#define NN 3136
#define CC 384
#define HH 8
#define HD 48
#define NT 196
#define C2 768
#define ROWW 56
#define EPSL 1e-6f
#define NOFF 169

typedef unsigned long long u64;

// packed fp32x2 FMA (Blackwell FFMA2 path; scalar-FFMA is half-rate rt=2)
__device__ __forceinline__ void ffma2(u64& d, u64 a, u64 b) {
    asm("fma.rn.f32x2 %0, %1, %2, %0;" : "+l"(d) : "l"(a), "l"(b));
}
__device__ __forceinline__ u64 pack2(float lo, float hi) {
    u64 r; asm("mov.b64 %0, {%1, %2};" : "=l"(r) : "f"(lo), "f"(hi)); return r;
}
__device__ __forceinline__ float2 unpack2(u64 v) {
    float2 f; asm("mov.b64 {%0, %1}, %2;" : "=f"(f.x), "=f"(f.y) : "l"(v)); return f;
}

// ---------------- scratch (static device globals; no allocation allowed) ----
__device__ float g_mu[BB * NN];
__device__ float g_rs[BB * NN];
__device__ float g_k[(size_t)BB * NN * CC];     // [b][n][h*HD+d]
__device__ float g_v[(size_t)BB * NN * CC];
__device__ float g_qc1[BB * NT * CC];           // attn1 output
__device__ float g_hm[BB * NT * C2];            // MLP hidden
__device__ float g_qc2[BB * NT * CC];           // MLP output (q_cond2)
__device__ float g_att[BB * NT * CC];           // attn3 output (pre-proj)
__device__ int   g_cent[BB * NT];               // centroid_idx

// ---------------- kernel 1: layernorm row stats --------------------------
__global__ void ln_stats_kernel(const float* __restrict__ x) {
    int row  = blockIdx.x * 8 + (threadIdx.x >> 5);
    int lane = threadIdx.x & 31;
    if (row >= BB * NN) return;
    const float* xr = x + (size_t)row * CC;
    float s = 0.f, sq = 0.f;
    #pragma unroll
    for (int j = 0; j < 3; j++) {               // 384 = 32 lanes * 3 * float4
        float4 v = *(const float4*)(xr + (j * 32 + lane) * 4);
        s  += v.x + v.y + v.z + v.w;
        sq += v.x * v.x + v.y * v.y + v.z * v.z + v.w * v.w;
    }
    #pragma unroll
    for (int o = 16; o > 0; o >>= 1) {
        s  += __shfl_xor_sync(0xffffffffu, s,  o);
        sq += __shfl_xor_sync(0xffffffffu, sq, o);
    }
    if (lane == 0) {
        float mu  = s / (float)CC;
        float var = sq / (float)CC - mu * mu;
        g_mu[row] = mu;
        g_rs[row] = rsqrtf(var + EPSL);
    }
}

// ---------------- double-buffered SGEMM w/ packed f32x2 FMA ----------------
// BM=BN=128, BK=16, 256 threads, 8x8 per-thread tile (as 8x4 f32x2 pairs).
// MODE 0: LN applied on A-load; epilogue splits cols -> g_k / g_v.
// MODE 1: +bias, exact gelu. MODE 2: +bias.
template <int MODE>
__global__ void __launch_bounds__(256, 2) gemm_db(
    const float* __restrict__ A, const float* __restrict__ W,
    float* __restrict__ O1, float* __restrict__ O2,
    const float* __restrict__ bias,
    const float* __restrict__ lnw, const float* __restrict__ lnb,
    int M, int Ncol, int K)
{
    __shared__ __align__(16) float As[2][16][128];
    __shared__ __align__(16) float Bs[2][16][128];

    const int tid     = threadIdx.x;
    const int rowBase = blockIdx.y * 128;
    const int colBase = blockIdx.x * 128;

    const int ldRow = tid & 127;          // A row / W col within tile
    const int ldK   = (tid >> 7) * 8;     // 0 or 8

    float lm = 0.f, lr = 0.f;
    if (MODE == 0) {
        lm = g_mu[rowBase + ldRow];
        lr = g_rs[rowBase + ldRow];
    }
    const float* Ap = A + (size_t)(rowBase + ldRow) * K + ldK;
    const float* Wp = W + (size_t)(colBase + ldRow) * K + ldK;

    u64 acc2[8][4];
    #pragma unroll
    for (int i = 0; i < 8; i++)
        #pragma unroll
        for (int j = 0; j < 4; j++) acc2[i][j] = 0ULL;   // two packed 0.0f

    const int ty = tid >> 4, tx = tid & 15;
    const int ntiles = K >> 4;

    // ---- prologue: tile 0 straight to smem buf 0
    {
        float4 a0 = *(const float4*)(Ap);
        float4 a1 = *(const float4*)(Ap + 4);
        if (MODE == 0) {
            float4 w0 = *(const float4*)(lnw + ldK);
            float4 w1 = *(const float4*)(lnw + ldK + 4);
            float4 b0 = *(const float4*)(lnb + ldK);
            float4 b1 = *(const float4*)(lnb + ldK + 4);
            a0.x = (a0.x - lm) * lr * w0.x + b0.x;
            a0.y = (a0.y - lm) * lr * w0.y + b0.y;
            a0.z = (a0.z - lm) * lr * w0.z + b0.z;
            a0.w = (a0.w - lm) * lr * w0.w + b0.w;
            a1.x = (a1.x - lm) * lr * w1.x + b1.x;
            a1.y = (a1.y - lm) * lr * w1.y + b1.y;
            a1.z = (a1.z - lm) * lr * w1.z + b1.z;
            a1.w = (a1.w - lm) * lr * w1.w + b1.w;
        }
        float4 b0 = *(const float4*)(Wp);
        float4 b1 = *(const float4*)(Wp + 4);
        As[0][ldK + 0][ldRow] = a0.x; As[0][ldK + 1][ldRow] = a0.y;
        As[0][ldK + 2][ldRow] = a0.z; As[0][ldK + 3][ldRow] = a0.w;
        As[0][ldK + 4][ldRow] = a1.x; As[0][ldK + 5][ldRow] = a1.y;
        As[0][ldK + 6][ldRow] = a1.z; As[0][ldK + 7][ldRow] = a1.w;
        Bs[0][ldK + 0][ldRow] = b0.x; Bs[0][ldK + 1][ldRow] = b0.y;
        Bs[0][ldK + 2][ldRow] = b0.z; Bs[0][ldK + 3][ldRow] = b0.w;
        Bs[0][ldK + 4][ldRow] = b1.x; Bs[0][ldK + 5][ldRow] = b1.y;
        Bs[0][ldK + 6][ldRow] = b1.z; Bs[0][ldK + 7][ldRow] = b1.w;
    }
    __syncthreads();

    int buf = 0;
    for (int t = 0; t < ntiles; t++) {
        float4 pa0, pa1, pb0, pb1;
        const bool havenext = (t + 1 < ntiles);
        if (havenext) {
            const int kof = (t + 1) << 4;
            pa0 = *(const float4*)(Ap + kof);
            pa1 = *(const float4*)(Ap + kof + 4);
            pb0 = *(const float4*)(Wp + kof);
            pb1 = *(const float4*)(Wp + kof + 4);
        }

        #pragma unroll
        for (int k = 0; k < 16; k++) {
            float4 a0 = *(const float4*)&As[buf][k][ty * 8];
            float4 a1 = *(const float4*)&As[buf][k][ty * 8 + 4];
            // B pairs: adjacent floats in smem ARE the packed layout
            const u64* bp = (const u64*)&Bs[buf][k][tx * 8];
            u64 rb0 = bp[0], rb1 = bp[1], rb2 = bp[2], rb3 = bp[3];
            u64 ra2[8];
            ra2[0] = pack2(a0.x, a0.x); ra2[1] = pack2(a0.y, a0.y);
            ra2[2] = pack2(a0.z, a0.z); ra2[3] = pack2(a0.w, a0.w);
            ra2[4] = pack2(a1.x, a1.x); ra2[5] = pack2(a1.y, a1.y);
            ra2[6] = pack2(a1.z, a1.z); ra2[7] = pack2(a1.w, a1.w);
            #pragma unroll
            for (int i = 0; i < 8; i++) {
                ffma2(acc2[i][0], ra2[i], rb0);
                ffma2(acc2[i][1], ra2[i], rb1);
                ffma2(acc2[i][2], ra2[i], rb2);
                ffma2(acc2[i][3], ra2[i], rb3);
            }
        }

        if (havenext) {
            const int nb  = buf ^ 1;
            const int kof = (t + 1) << 4;
            if (MODE == 0) {
                float4 w0 = *(const float4*)(lnw + kof + ldK);
                float4 w1 = *(const float4*)(lnw + kof + ldK + 4);
                float4 lb0 = *(const float4*)(lnb + kof + ldK);
                float4 lb1 = *(const float4*)(lnb + kof + ldK + 4);
                pa0.x = (pa0.x - lm) * lr * w0.x + lb0.x;
                pa0.y = (pa0.y - lm) * lr * w0.y + lb0.y;
                pa0.z = (pa0.z - lm) * lr * w0.z + lb0.z;
                pa0.w = (pa0.w - lm) * lr * w0.w + lb0.w;
                pa1.x = (pa1.x - lm) * lr * w1.x + lb1.x;
                pa1.y = (pa1.y - lm) * lr * w1.y + lb1.y;
                pa1.z = (pa1.z - lm) * lr * w1.z + lb1.z;
                pa1.w = (pa1.w - lm) * lr * w1.w + lb1.w;
            }
            As[nb][ldK + 0][ldRow] = pa0.x; As[nb][ldK + 1][ldRow] = pa0.y;
            As[nb][ldK + 2][ldRow] = pa0.z; As[nb][ldK + 3][ldRow] = pa0.w;
            As[nb][ldK + 4][ldRow] = pa1.x; As[nb][ldK + 5][ldRow] = pa1.y;
            As[nb][ldK + 6][ldRow] = pa1.z; As[nb][ldK + 7][ldRow] = pa1.w;
            Bs[nb][ldK + 0][ldRow] = pb0.x; Bs[nb][ldK + 1][ldRow] = pb0.y;
            Bs[nb][ldK + 2][ldRow] = pb0.z; Bs[nb][ldK + 3][ldRow] = pb0.w;
            Bs[nb][ldK + 4][ldRow] = pb1.x; Bs[nb][ldK + 5][ldRow] = pb1.y;
            Bs[nb][ldK + 6][ldRow] = pb1.z; Bs[nb][ldK + 7][ldRow] = pb1.w;
            __syncthreads();
        }
        buf ^= 1;
    }

    #pragma unroll
    for (int i = 0; i < 8; i++) {
        const int row = rowBase + ty * 8 + i;
        #pragma unroll
        for (int jp = 0; jp < 4; jp++) {
            float2 vv = unpack2(acc2[i][jp]);
            #pragma unroll
            for (int half = 0; half < 2; half++) {
                const int col = colBase + tx * 8 + jp * 2 + half;
                float v = half ? vv.y : vv.x;
                if (MODE == 0) {
                    if (col < CC) O1[(size_t)row * CC + col]        = v;
                    else          O2[(size_t)row * CC + (col - CC)] = v;
                } else if (MODE == 1) {
                    v += bias[col];
                    v = v * normcdff(v);           // exact gelu: x * Phi(x)
                    O1[(size_t)row * Ncol + col] = v;
                } else {
                    v += bias[col];
                    O1[(size_t)row * Ncol + col] = v;
                }
            }
        }
    }
}

// ---------------- kernel 3: attn1 + q_cond1 (online softmax, no spill) -----
__global__ void attn1_kernel(const float* __restrict__ q,
                             const int* __restrict__ idx_sub) {
    extern __shared__ float sm[];
    float* ks = sm;               // [NT*HD]
    float* vs = sm + NT * HD;     // [NT*HD]
    const int b = blockIdx.x / HH;
    const int h = blockIdx.x % HH;
    const int tid = threadIdx.x;

    for (int i = tid; i < NT * HD; i += blockDim.x) {
        const int n = i / HD, d = i % HD;
        const size_t src = (size_t)(b * NN + idx_sub[n]) * CC + h * HD + d;
        ks[i] = g_k[src];
        vs[i] = g_v[src];
    }
    __syncthreads();

    const int m = tid;
    if (m < NT) {
        const float scale = rsqrtf((float)HD);
        float qr[HD];
        const float* qp = q + (m * HH + h) * HD;
        #pragma unroll
        for (int d = 0; d < HD; d++) qr[d] = qp[d] * scale;

        float mx = -1e30f, ssum = 0.f;
        float accd[HD];
        #pragma unroll
        for (int d = 0; d < HD; d++) accd[d] = 0.f;

        for (int n = 0; n < NT; n++) {
            const float* kp = ks + n * HD;
            float s = 0.f;
            #pragma unroll
            for (int d = 0; d < HD; d++) s += qr[d] * kp[d];
            if (s > mx) {
                const float c = expf(mx - s);   // first iter: exp(-inf)=0
                ssum *= c;
                #pragma unroll
                for (int d = 0; d < HD; d++) accd[d] *= c;
                mx = s;
            }
            const float w = expf(s - mx);
            ssum += w;
            const float* vp = vs + n * HD;
            #pragma unroll
            for (int d = 0; d < HD; d++) accd[d] += w * vp[d];
        }
        const float inv = 1.f / ssum;
        float* op = g_qc1 + (size_t)(b * NT + m) * CC + h * HD;
        #pragma unroll
        for (int d = 0; d < HD; d++) op[d] = accd[d] * inv;
    }
}

// ---------------- kernel 6: centroid (attn2 argmax) ------------------------
// mean over h of per-head dots == (1/H) * full-C dot -> argmax ignores 1/H.
__global__ void centroid_kernel(const int* __restrict__ idxs) {
    __shared__ float sq[CC];
    __shared__ float sval[256];
    __shared__ int   sidx[256];
    const int bm = blockIdx.x;       // b*NT + m
    const int b  = bm / NT;
    const int tid = threadIdx.x;

    const float* qp = g_qc2 + (size_t)bm * CC;
    for (int i = tid; i < CC; i += blockDim.x) sq[i] = qp[i];
    __syncthreads();

    float best = -1e30f;
    int   bi   = 0x7fffffff;
    for (int n = tid; n < NT; n += blockDim.x) {
        const float* kp = g_k + (size_t)(b * NN + idxs[n]) * CC;
        float s = 0.f;
        for (int c = 0; c < CC; c += 4) {
            float4 k4 = *(const float4*)(kp + c);
            s += sq[c] * k4.x + sq[c + 1] * k4.y + sq[c + 2] * k4.z + sq[c + 3] * k4.w;
        }
        if (s > best || (s == best && n < bi)) { best = s; bi = n; }
    }
    sval[tid] = best; sidx[tid] = bi;
    __syncthreads();
    for (int o = 128; o > 0; o >>= 1) {
        if (tid < o) {
            const float v2 = sval[tid + o];
            const int   i2 = sidx[tid + o];
            if (v2 > sval[tid] || (v2 == sval[tid] && i2 < sidx[tid])) {
                sval[tid] = v2; sidx[tid] = i2;
            }
        }
        __syncthreads();
    }
    if (tid == 0) g_cent[bm] = idxs[sidx[0]];
}

// ---------------- kernel 7: sparse attn3 + AV ------------------------------
// exp(NEG + s - max) underflows to exactly 0.0f, so restricting softmax/AV to
// the <=169 allowed positions is bit-equivalent to the dense reference.
__global__ void __launch_bounds__(192) attn3_kernel() {
    __shared__ float sq[CC];
    __shared__ int   s_adj[NOFF];
    __shared__ unsigned char s_uniq[NOFF];
    __shared__ float s_w[NOFF];
    __shared__ float s_part[4][HD];
    __shared__ float s_sum;

    const int bm = blockIdx.x;
    const int b  = bm / NT;
    const int tid = threadIdx.x;
    const float scale = rsqrtf((float)HD);

    const float* qp = g_qc2 + (size_t)bm * CC;
    for (int i = tid; i < CC; i += blockDim.x) sq[i] = qp[i];
    const int cent = g_cent[bm];
    if (tid < NOFF) {
        const int r = tid / 13 - 6, c = tid % 13 - 6;
        int a = cent + (c - ROWW * r);
        a = max(0, min(NN - 1, a));
        s_adj[tid] = a;
    }
    __syncthreads();
    if (tid < NOFF) {
        const int a = s_adj[tid];
        unsigned char u = 1;
        for (int j = 0; j < tid; j++) if (s_adj[j] == a) { u = 0; break; }
        s_uniq[tid] = u;
    }
    __syncthreads();

    for (int h = 0; h < HH; h++) {
        const float* qh = sq + h * HD;
        for (int n = tid; n < NOFF; n += blockDim.x) {
            float s = -1e30f;
            if (s_uniq[n]) {
                const float* kp = g_k + (size_t)(b * NN + s_adj[n]) * CC + h * HD;
                float acc = 0.f;
                #pragma unroll
                for (int c = 0; c < HD; c += 4) {
                    float4 k4 = *(const float4*)(kp + c);
                    acc += qh[c] * k4.x + qh[c + 1] * k4.y + qh[c + 2] * k4.z + qh[c + 3] * k4.w;
                }
                s = acc * scale;
            }
            s_w[n] = s;
        }
        __syncthreads();
        if (tid < 32) {
            float mx = -1e30f;
            for (int n = tid; n < NOFF; n += 32) mx = fmaxf(mx, s_w[n]);
            #pragma unroll
            for (int o = 16; o > 0; o >>= 1) mx = fmaxf(mx, __shfl_xor_sync(0xffffffffu, mx, o));
            float sum = 0.f;
            for (int n = tid; n < NOFF; n += 32) {
                const float w = expf(s_w[n] - mx);   // dup: exp(-1e30-mx) == 0
                s_w[n] = w;
                sum += w;
            }
            #pragma unroll
            for (int o = 16; o > 0; o >>= 1) sum += __shfl_xor_sync(0xffffffffu, sum, o);
            if (tid == 0) s_sum = sum;
        }
        __syncthreads();
        const float inv = 1.f / s_sum;
        const int g = tid / HD;          // 0..3
        const int d = tid % HD;
        float acc = 0.f;
        for (int n = g; n < NOFF; n += 4)
            acc += s_w[n] * g_v[(size_t)(b * NN + s_adj[n]) * CC + h * HD + d];
        s_part[g][d] = acc;
        __syncthreads();
        if (tid < HD) {
            const float o = (s_part[0][tid] + s_part[1][tid] +
                             s_part[2][tid] + s_part[3][tid]) * inv;
            g_att[(size_t)bm * CC + h * HD + tid] = o;
        }
        __syncthreads();
    }
}

// ---------------- launch ---------------------------------------------------
extern "C" void kernel_launch(void* const* d_in, const int* in_sizes, int n_in,
                              void* d_out, int out_size) {
    const float* x      = (const float*)d_in[0];
    const float* q      = (const float*)d_in[1];
    const float* kv_w   = (const float*)d_in[2];
    const float* proj_w = (const float*)d_in[3];
    const float* proj_b = (const float*)d_in[4];
    const float* ln_w   = (const float*)d_in[5];
    const float* ln_b   = (const float*)d_in[6];
    const float* fc1_w  = (const float*)d_in[7];
    const float* fc1_b  = (const float*)d_in[8];
    const float* fc2_w  = (const float*)d_in[9];
    const float* fc2_b  = (const float*)d_in[10];
    const int* idx_sub  = (const int*)d_in[11];
    const int* idxs     = (const int*)d_in[12];
    float* out = (float*)d_out;

    float *pk, *pv, *pqc1, *phm, *pqc2, *patt;
    cudaGetSymbolAddress((void**)&pk,   g_k);
    cudaGetSymbolAddress((void**)&pv,   g_v);
    cudaGetSymbolAddress((void**)&pqc1, g_qc1);
    cudaGetSymbolAddress((void**)&phm,  g_hm);
    cudaGetSymbolAddress((void**)&pqc2, g_qc2);
    cudaGetSymbolAddress((void**)&patt, g_att);

    // 1. LN row stats
    ln_stats_kernel<<<(BB * NN) / 8, 256>>>(x);

    // 2. fused LN + KV projection (the 59-GFLOP GEMM)
    gemm_db<0><<<dim3(C2 / 128, (BB * NN) / 128), 256>>>(
        x, kv_w, pk, pv, nullptr, ln_w, ln_b, BB * NN, C2, CC);

    // 3. attn1 + q_cond1
    cudaFuncSetAttribute(attn1_kernel,
                         cudaFuncAttributeMaxDynamicSharedMemorySize,
                         2 * NT * HD * (int)sizeof(float));
    attn1_kernel<<<BB * HH, 256, 2 * NT * HD * sizeof(float)>>>(q, idx_sub);

    // 4. MLP
    gemm_db<1><<<dim3(C2 / 128, (BB * NT) / 128), 256>>>(
        pqc1, fc1_w, phm, nullptr, fc1_b, nullptr, nullptr, BB * NT, C2, CC);
    gemm_db<2><<<dim3(CC / 128, (BB * NT) / 128), 256>>>(
        phm, fc2_w, pqc2, nullptr, fc2_b, nullptr, nullptr, BB * NT, CC, C2);

    // 5. centroid argmax (attn2 collapsed to full-C dot)
    centroid_kernel<<<BB * NT, 256>>>(idxs);

    // 6. sparse attn3 + AV
    attn3_kernel<<<BB * NT, 192>>>();

    // 7. output projection
    gemm_db<2><<<dim3(CC / 128, (BB * NT) / 128), 256>>>(
        patt, proj_w, out, nullptr, proj_b, nullptr, nullptr, BB * NT, CC, CC);
}